// round 5
// baseline (speedup 1.0000x reference)
#include <cuda_runtime.h>
#include <math.h>

#define PI_C 3.14159f
#define TILE_PITCH 129                     // odd pitch kills stride-128 bank conflicts
#define TILE_BYTES (128 * TILE_PITCH * 4)  // 66048

// ---------------- scratch (allocation-free rule: __device__ globals) --------
// mlp1 partial sums: [kc][b*256+j], kc in 0..3 (kc=0 includes bias b1)
__device__ float g_p1[4 * 8 * 256];

// ---------------- kernel 1: partial p = pc @ W1 (+b1), split over k ---------
// grid: (8 jc, 4 kc) = 32 blocks, 256 threads = 32 jl x 8 ks.
// Each block: 32 j-columns, 64-k slice, all 8 batches in registers.
__global__ void mlp1_partial_kernel(const float* __restrict__ pc,
                                    const float* __restrict__ W1,
                                    const float* __restrict__ b1) {
    __shared__ float spc[8 * 64];           // pc slice [b][k_local]
    __shared__ float part[8 * 8 * 32];      // [ks][b][jl]
    const int tid = threadIdx.x;
    const int jl = tid & 31;
    const int ks = tid >> 5;
    const int jc = blockIdx.x;
    const int kc = blockIdx.y;
    const int j = jc * 32 + jl;
    const int kbase = kc * 64;

    #pragma unroll
    for (int i = tid; i < 512; i += 256)
        spc[i] = pc[(i >> 6) * 256 + kbase + (i & 63)];
    __syncthreads();

    float acc[8];
    #pragma unroll
    for (int b = 0; b < 8; ++b) acc[b] = 0.0f;

    #pragma unroll
    for (int kk = 0; kk < 8; ++kk) {
        const int kl = ks * 8 + kk;                 // 0..63
        const float w = W1[(kbase + kl) * 256 + j]; // coalesced over jl
        #pragma unroll
        for (int b = 0; b < 8; ++b) acc[b] = fmaf(spc[b * 64 + kl], w, acc[b]);
    }
    #pragma unroll
    for (int b = 0; b < 8; ++b) part[(ks * 8 + b) * 32 + jl] = acc[b];
    __syncthreads();

    const int jl2 = tid & 31;
    const int b2 = tid >> 5;
    float sum = (kc == 0) ? b1[jc * 32 + jl2] : 0.0f;
    #pragma unroll
    for (int k2 = 0; k2 < 8; ++k2) sum += part[(k2 * 8 + b2) * 32 + jl2];
    g_p1[kc * 2048 + b2 * 256 + jc * 32 + jl2] = sum;
}

// ---------------- kernel 2: fused params + affine bilinear resample ---------
// grid: B*D = 2048 blocks, 512 threads, pitched 66KB smem tile.
// Preamble (hidden under stage-in): warps 0-3 compute the 4 per-(b,d) dot
// products (mlp2), reduce, fold transcendentals into 6 affine constants.
__global__ __launch_bounds__(512) void resample_kernel(
        const float* __restrict__ fm, float* __restrict__ out,
        const float* __restrict__ Ws, const float* __restrict__ bs,
        const float* __restrict__ Wr, const float* __restrict__ br,
        const float* __restrict__ Wt, const float* __restrict__ bt) {
    extern __shared__ float tile[];           // 128 rows x 129 pitch
    __shared__ float s_raw[4];
    __shared__ float s_cf[6];                 // Ax, Ay, A0, Bx, By, B0
    const int n = blockIdx.x;                 // n = b*256 + d
    const int tid = threadIdx.x;
    const int b = n >> 8;
    const int d = n & 255;
    const float* __restrict__ img = fm + (size_t)n * 16384;

    // ---- stage-in: coalesced float4 GMEM reads -> pitched SMEM stores ----
    {
        const float4* __restrict__ i4 = (const float4*)img;
        #pragma unroll
        for (int i = tid; i < 4096; i += 512) {
            const float4 v = i4[i];
            float* dst = &tile[(i >> 5) * TILE_PITCH + (i & 31) * 4];
            dst[0] = v.x; dst[1] = v.y; dst[2] = v.z; dst[3] = v.w;
        }
    }

    // ---- param dot-products on warps 0-3 (one family each), overlapped ----
    if (tid < 128) {
        const int f = tid >> 5;               // family: s, r, t0, t1
        const int lane = tid & 31;
        const float* __restrict__ pp = g_p1 + b * 256;

        const float* __restrict__ Wcol;
        int stride;
        if (f == 0)      { Wcol = Ws + d;          stride = 256; }
        else if (f == 1) { Wcol = Wr + d;          stride = 256; }
        else if (f == 2) { Wcol = Wt + 2 * d;      stride = 512; }
        else             { Wcol = Wt + 2 * d + 1;  stride = 512; }

        float acc = 0.0f;
        #pragma unroll
        for (int i = 0; i < 8; ++i) {
            const int k = lane + 32 * i;
            float pk = pp[k] + pp[2048 + k] + pp[2 * 2048 + k] + pp[3 * 2048 + k];
            pk = fmaxf(pk, 0.0f);             // relu(b1 + full k-sum)
            acc = fmaf(pk, Wcol[(size_t)k * stride], acc);
        }
        #pragma unroll
        for (int o = 16; o > 0; o >>= 1)
            acc += __shfl_xor_sync(0xFFFFFFFFu, acc, o);

        if (lane == 0) {
            float bias;
            if (f == 0)      bias = bs[d];
            else if (f == 1) bias = br[d];
            else if (f == 2) bias = bt[2 * d];
            else             bias = bt[2 * d + 1];
            s_raw[f] = acc + bias;
        }
        asm volatile("bar.sync 1, 128;" ::: "memory");   // warps 0-3 only

        if (tid == 0) {
            const float scale = 2.0f / (1.0f + expf(-s_raw[0]));
            const float ang = tanhf(s_raw[1]) * PI_C;
            const float a = cosf(ang) * scale;
            const float s = sinf(ang) * scale;
            const float tx = tanhf(s_raw[2]);
            const float ty = tanhf(s_raw[3]);
            const float k64 = 64.0f * (2.0f / 127.0f);
            s_cf[0] = a * k64;                        // Ax
            s_cf[1] = -s * k64;                       // Ay
            s_cf[2] = (tx - a + s) * 64.0f + 63.5f;   // A0
            s_cf[3] = s * k64;                        // Bx
            s_cf[4] = a * k64;                        // By
            s_cf[5] = (ty - s - a) * 64.0f + 63.5f;   // B0
        }
    }
    __syncthreads();

    const float Ax = s_cf[0], Ay = s_cf[1], A0 = s_cf[2];
    const float Bx = s_cf[3], By = s_cf[4], B0 = s_cf[5];

    // ---- sampling: 4-pixel quads, float4 stores ----
    float4* __restrict__ o4 = (float4*)(out + (size_t)n * 16384);
    #pragma unroll 2
    for (int i = tid; i < 4096; i += 512) {
        const float xq = (float)((i & 31) << 2);
        const float fy = (float)(i >> 5);
        const float baseX = fmaf(Ay, fy, A0);
        const float baseY = fmaf(By, fy, B0);
        float4 r;
        float* rp = &r.x;
        #pragma unroll
        for (int q = 0; q < 4; ++q) {
            const float xf = xq + (float)q;
            float px = fmaf(Ax, xf, baseX);
            float py = fmaf(Bx, xf, baseY);
            px = fminf(fmaxf(px, 0.0f), 127.0f);   // padding_mode='border'
            py = fminf(fmaxf(py, 0.0f), 127.0f);
            const float x0f = floorf(px);
            const float y0f = floorf(py);
            const float wx = px - x0f;
            const float wy = py - y0f;
            const int x0 = (int)x0f;
            const int y0 = (int)y0f;
            const int x1 = min(x0 + 1, 127);
            const int y1 = min(y0 + 1, 127);
            const int r0 = y0 * TILE_PITCH;
            const int r1 = y1 * TILE_PITCH;
            const float v00 = tile[r0 + x0];
            const float v01 = tile[r0 + x1];
            const float v10 = tile[r1 + x0];
            const float v11 = tile[r1 + x1];
            const float top = fmaf(wx, v01 - v00, v00);
            const float bot = fmaf(wx, v11 - v10, v10);
            rp[q] = fmaf(wy, bot - top, top);
        }
        o4[i] = r;
    }
}

// ---------------- launch -----------------------------------------------------
extern "C" void kernel_launch(void* const* d_in, const int* in_sizes, int n_in,
                              void* d_out, int out_size) {
    const float* feature_map = (const float*)d_in[0];   // (8,256,128,128)
    const float* para_code   = (const float*)d_in[1];   // (8,256)
    const float* W1 = (const float*)d_in[2];            // (256,256)
    const float* b1 = (const float*)d_in[3];            // (256,)
    const float* Ws = (const float*)d_in[4];            // (256,256)
    const float* bs = (const float*)d_in[5];            // (256,)
    const float* Wr = (const float*)d_in[6];            // (256,256)
    const float* br = (const float*)d_in[7];            // (256,)
    const float* Wt = (const float*)d_in[8];            // (256,512)
    const float* bt = (const float*)d_in[9];            // (512,)
    float* out = (float*)d_out;

    cudaFuncSetAttribute(resample_kernel,
                         cudaFuncAttributeMaxDynamicSharedMemorySize, TILE_BYTES);

    mlp1_partial_kernel<<<dim3(8, 4), 256>>>(para_code, W1, b1);
    resample_kernel<<<2048, 512, TILE_BYTES>>>(feature_map, out,
                                               Ws, bs, Wr, br, Wt, bt);
}

// round 8
// speedup vs baseline: 1.0020x; 1.0020x over previous
#include <cuda_runtime.h>
#include <math.h>

#define PI_C 3.14159f
#define TILE_PITCH 129                     // odd pitch kills stride-128 bank conflicts
#define TILE_BYTES (128 * TILE_PITCH * 4)  // 66048

// ---------------- scratch (allocation-free rule: __device__ globals) --------
// mlp1 partial sums: [kc][b*256+j], kc in 0..3 (kc=0 includes bias b1)
__device__ float g_p1[4 * 8 * 256];

// ---------------- kernel 1: partial p = pc @ W1 (+b1), split over k ---------
// grid: (8 jc, 4 kc) = 32 blocks, 256 threads = 32 jl x 8 ks.
// Each block: 32 j-columns, 64-k slice, all 8 batches in registers.
__global__ void mlp1_partial_kernel(const float* __restrict__ pc,
                                    const float* __restrict__ W1,
                                    const float* __restrict__ b1) {
    __shared__ float spc[8 * 64];           // pc slice [b][k_local]
    __shared__ float part[8 * 8 * 32];      // [ks][b][jl]
    const int tid = threadIdx.x;
    const int jl = tid & 31;
    const int ks = tid >> 5;
    const int jc = blockIdx.x;
    const int kc = blockIdx.y;
    const int j = jc * 32 + jl;
    const int kbase = kc * 64;

    #pragma unroll
    for (int i = tid; i < 512; i += 256)
        spc[i] = pc[(i >> 6) * 256 + kbase + (i & 63)];
    __syncthreads();

    float acc[8];
    #pragma unroll
    for (int b = 0; b < 8; ++b) acc[b] = 0.0f;

    #pragma unroll
    for (int kk = 0; kk < 8; ++kk) {
        const int kl = ks * 8 + kk;                 // 0..63
        const float w = W1[(kbase + kl) * 256 + j]; // coalesced over jl
        #pragma unroll
        for (int b = 0; b < 8; ++b) acc[b] = fmaf(spc[b * 64 + kl], w, acc[b]);
    }
    #pragma unroll
    for (int b = 0; b < 8; ++b) part[(ks * 8 + b) * 32 + jl] = acc[b];
    __syncthreads();

    const int jl2 = tid & 31;
    const int b2 = tid >> 5;
    float sum = (kc == 0) ? b1[jc * 32 + jl2] : 0.0f;
    #pragma unroll
    for (int k2 = 0; k2 < 8; ++k2) sum += part[(k2 * 8 + b2) * 32 + jl2];
    g_p1[kc * 2048 + b2 * 256 + jc * 32 + jl2] = sum;
}

// ---------------- kernel 2: fused params + affine bilinear resample ---------
// grid: B*D = 2048 blocks, 512 threads, pitched 66KB smem tile.
// Preamble (hidden under stage-in): warps 0-3 compute the 4 per-(b,d) dot
// products (mlp2), reduce, fold transcendentals into 6 affine constants.
__global__ __launch_bounds__(512) void resample_kernel(
        const float* __restrict__ fm, float* __restrict__ out,
        const float* __restrict__ Ws, const float* __restrict__ bs,
        const float* __restrict__ Wr, const float* __restrict__ br,
        const float* __restrict__ Wt, const float* __restrict__ bt) {
    extern __shared__ float tile[];           // 128 rows x 129 pitch
    __shared__ float s_raw[4];
    __shared__ float s_cf[6];                 // Ax, Ay, A0, Bx, By, B0
    const int n = blockIdx.x;                 // n = b*256 + d
    const int tid = threadIdx.x;
    const int b = n >> 8;
    const int d = n & 255;
    const float* __restrict__ img = fm + (size_t)n * 16384;

    // ---- stage-in: coalesced float4 GMEM reads -> pitched SMEM stores ----
    {
        const float4* __restrict__ i4 = (const float4*)img;
        #pragma unroll
        for (int i = tid; i < 4096; i += 512) {
            const float4 v = i4[i];
            float* dst = &tile[(i >> 5) * TILE_PITCH + (i & 31) * 4];
            dst[0] = v.x; dst[1] = v.y; dst[2] = v.z; dst[3] = v.w;
        }
    }

    // ---- param dot-products on warps 0-3 (one family each), overlapped ----
    if (tid < 128) {
        const int f = tid >> 5;               // family: s, r, t0, t1
        const int lane = tid & 31;
        const float* __restrict__ pp = g_p1 + b * 256;

        const float* __restrict__ Wcol;
        int stride;
        if (f == 0)      { Wcol = Ws + d;          stride = 256; }
        else if (f == 1) { Wcol = Wr + d;          stride = 256; }
        else if (f == 2) { Wcol = Wt + 2 * d;      stride = 512; }
        else             { Wcol = Wt + 2 * d + 1;  stride = 512; }

        float acc = 0.0f;
        #pragma unroll
        for (int i = 0; i < 8; ++i) {
            const int k = lane + 32 * i;
            float pk = pp[k] + pp[2048 + k] + pp[2 * 2048 + k] + pp[3 * 2048 + k];
            pk = fmaxf(pk, 0.0f);             // relu(b1 + full k-sum)
            acc = fmaf(pk, Wcol[(size_t)k * stride], acc);
        }
        #pragma unroll
        for (int o = 16; o > 0; o >>= 1)
            acc += __shfl_xor_sync(0xFFFFFFFFu, acc, o);

        if (lane == 0) {
            float bias;
            if (f == 0)      bias = bs[d];
            else if (f == 1) bias = br[d];
            else if (f == 2) bias = bt[2 * d];
            else             bias = bt[2 * d + 1];
            s_raw[f] = acc + bias;
        }
    }
    __syncthreads();   // s_raw visible to all (stage-in also done by now)

    if (tid == 0) {
        const float scale = 2.0f / (1.0f + expf(-s_raw[0]));
        const float ang = tanhf(s_raw[1]) * PI_C;
        const float a = cosf(ang) * scale;
        const float s = sinf(ang) * scale;
        const float tx = tanhf(s_raw[2]);
        const float ty = tanhf(s_raw[3]);
        const float k64 = 64.0f * (2.0f / 127.0f);
        s_cf[0] = a * k64;                        // Ax
        s_cf[1] = -s * k64;                       // Ay
        s_cf[2] = (tx - a + s) * 64.0f + 63.5f;   // A0
        s_cf[3] = s * k64;                        // Bx
        s_cf[4] = a * k64;                        // By
        s_cf[5] = (ty - s - a) * 64.0f + 63.5f;   // B0
    }
    __syncthreads();

    const float Ax = s_cf[0], Ay = s_cf[1], A0 = s_cf[2];
    const float Bx = s_cf[3], By = s_cf[4], B0 = s_cf[5];

    // ---- sampling: 4-pixel quads, float4 stores ----
    float4* __restrict__ o4 = (float4*)(out + (size_t)n * 16384);
    #pragma unroll 2
    for (int i = tid; i < 4096; i += 512) {
        const float xq = (float)((i & 31) << 2);
        const float fy = (float)(i >> 5);
        const float baseX = fmaf(Ay, fy, A0);
        const float baseY = fmaf(By, fy, B0);
        float4 r;
        float* rp = &r.x;
        #pragma unroll
        for (int q = 0; q < 4; ++q) {
            const float xf = xq + (float)q;
            float px = fmaf(Ax, xf, baseX);
            float py = fmaf(Bx, xf, baseY);
            px = fminf(fmaxf(px, 0.0f), 127.0f);   // padding_mode='border'
            py = fminf(fmaxf(py, 0.0f), 127.0f);
            const float x0f = floorf(px);
            const float y0f = floorf(py);
            const float wx = px - x0f;
            const float wy = py - y0f;
            const int x0 = (int)x0f;
            const int y0 = (int)y0f;
            const int x1 = min(x0 + 1, 127);
            const int y1 = min(y0 + 1, 127);
            const int r0 = y0 * TILE_PITCH;
            const int r1 = y1 * TILE_PITCH;
            const float v00 = tile[r0 + x0];
            const float v01 = tile[r0 + x1];
            const float v10 = tile[r1 + x0];
            const float v11 = tile[r1 + x1];
            const float top = fmaf(wx, v01 - v00, v00);
            const float bot = fmaf(wx, v11 - v10, v10);
            rp[q] = fmaf(wy, bot - top, top);
        }
        o4[i] = r;
    }
}

// ---------------- launch -----------------------------------------------------
extern "C" void kernel_launch(void* const* d_in, const int* in_sizes, int n_in,
                              void* d_out, int out_size) {
    const float* feature_map = (const float*)d_in[0];   // (8,256,128,128)
    const float* para_code   = (const float*)d_in[1];   // (8,256)
    const float* W1 = (const float*)d_in[2];            // (256,256)
    const float* b1 = (const float*)d_in[3];            // (256,)
    const float* Ws = (const float*)d_in[4];            // (256,256)
    const float* bs = (const float*)d_in[5];            // (256,)
    const float* Wr = (const float*)d_in[6];            // (256,256)
    const float* br = (const float*)d_in[7];            // (256,)
    const float* Wt = (const float*)d_in[8];            // (256,512)
    const float* bt = (const float*)d_in[9];            // (512,)
    float* out = (float*)d_out;

    cudaFuncSetAttribute(resample_kernel,
                         cudaFuncAttributeMaxDynamicSharedMemorySize, TILE_BYTES);

    mlp1_partial_kernel<<<dim3(8, 4), 256>>>(para_code, W1, b1);
    resample_kernel<<<2048, 512, TILE_BYTES>>>(feature_map, out,
                                               Ws, bs, Wr, br, Wt, bt);
}

// round 11
// speedup vs baseline: 1.0182x; 1.0162x over previous
#include <cuda_runtime.h>
#include <math.h>

#define PI_C 3.14159f
#define TILE_PITCH 129                     // odd pitch kills stride-128 bank conflicts
#define TILE_BYTES (128 * TILE_PITCH * 4)  // 66048

// ---------------- scratch (allocation-free rule: __device__ globals) --------
// mlp1 partial sums: [kc][b*256+j], kc in 0..3 (kc=0 includes bias b1)
__device__ float g_p1[4 * 8 * 256];

// ---------------- kernel 1: partial p = pc @ W1 (+b1), split over k ---------
// grid: (8 jc, 4 kc) = 32 blocks, 256 threads = 32 jl x 8 ks.
// Each block: 32 j-columns, 64-k slice, all 8 batches in registers.
__global__ void mlp1_partial_kernel(const float* __restrict__ pc,
                                    const float* __restrict__ W1,
                                    const float* __restrict__ b1) {
    __shared__ float spc[8 * 64];           // pc slice [b][k_local]
    __shared__ float part[8 * 8 * 32];      // [ks][b][jl]
    const int tid = threadIdx.x;
    const int jl = tid & 31;
    const int ks = tid >> 5;
    const int jc = blockIdx.x;
    const int kc = blockIdx.y;
    const int j = jc * 32 + jl;
    const int kbase = kc * 64;

    #pragma unroll
    for (int i = tid; i < 512; i += 256)
        spc[i] = pc[(i >> 6) * 256 + kbase + (i & 63)];
    __syncthreads();

    float acc[8];
    #pragma unroll
    for (int b = 0; b < 8; ++b) acc[b] = 0.0f;

    #pragma unroll
    for (int kk = 0; kk < 8; ++kk) {
        const int kl = ks * 8 + kk;                 // 0..63
        const float w = W1[(kbase + kl) * 256 + j]; // coalesced over jl
        #pragma unroll
        for (int b = 0; b < 8; ++b) acc[b] = fmaf(spc[b * 64 + kl], w, acc[b]);
    }
    #pragma unroll
    for (int b = 0; b < 8; ++b) part[(ks * 8 + b) * 32 + jl] = acc[b];
    __syncthreads();

    const int jl2 = tid & 31;
    const int b2 = tid >> 5;
    float sum = (kc == 0) ? b1[jc * 32 + jl2] : 0.0f;
    #pragma unroll
    for (int k2 = 0; k2 < 8; ++k2) sum += part[(k2 * 8 + b2) * 32 + jl2];
    g_p1[kc * 2048 + b2 * 256 + jc * 32 + jl2] = sum;
}

// ---------------- kernel 2: fused params + affine bilinear resample ---------
// grid: B*D = 2048 blocks, 512 threads, pitched 66KB smem tile.
// Preamble (hidden under stage-in): warps 0-3 compute the 4 per-(b,d) dot
// products (mlp2), reduce, fold transcendentals into 6 affine constants.
__global__ __launch_bounds__(512) void resample_kernel(
        const float* __restrict__ fm, float* __restrict__ out,
        const float* __restrict__ Ws, const float* __restrict__ bs,
        const float* __restrict__ Wr, const float* __restrict__ br,
        const float* __restrict__ Wt, const float* __restrict__ bt) {
    extern __shared__ float tile[];           // 128 rows x 129 pitch
    __shared__ float s_raw[4];
    __shared__ float s_cf[6];                 // Ax, Ay, A0, Bx, By, B0
    const int n = blockIdx.x;                 // n = b*256 + d
    const int tid = threadIdx.x;
    const int b = n >> 8;
    const int d = n & 255;
    const float* __restrict__ img = fm + (size_t)n * 16384;

    // ---- stage-in: coalesced float4 GMEM reads -> pitched SMEM stores ----
    {
        const float4* __restrict__ i4 = (const float4*)img;
        #pragma unroll
        for (int i = tid; i < 4096; i += 512) {
            const float4 v = i4[i];
            float* dst = &tile[(i >> 5) * TILE_PITCH + (i & 31) * 4];
            dst[0] = v.x; dst[1] = v.y; dst[2] = v.z; dst[3] = v.w;
        }
    }

    // ---- param dot-products on warps 0-3 (one family each), overlapped ----
    if (tid < 128) {
        const int f = tid >> 5;               // family: s, r, t0, t1
        const int lane = tid & 31;
        const float* __restrict__ pp = g_p1 + b * 256;

        const float* __restrict__ Wcol;
        int stride;
        if (f == 0)      { Wcol = Ws + d;          stride = 256; }
        else if (f == 1) { Wcol = Wr + d;          stride = 256; }
        else if (f == 2) { Wcol = Wt + 2 * d;      stride = 512; }
        else             { Wcol = Wt + 2 * d + 1;  stride = 512; }

        float acc = 0.0f;
        #pragma unroll
        for (int i = 0; i < 8; ++i) {
            const int k = lane + 32 * i;
            float pk = pp[k] + pp[2048 + k] + pp[2 * 2048 + k] + pp[3 * 2048 + k];
            pk = fmaxf(pk, 0.0f);             // relu(b1 + full k-sum)
            acc = fmaf(pk, Wcol[(size_t)k * stride], acc);
        }
        #pragma unroll
        for (int o = 16; o > 0; o >>= 1)
            acc += __shfl_xor_sync(0xFFFFFFFFu, acc, o);

        if (lane == 0) {
            float bias;
            if (f == 0)      bias = bs[d];
            else if (f == 1) bias = br[d];
            else if (f == 2) bias = bt[2 * d];
            else             bias = bt[2 * d + 1];
            s_raw[f] = acc + bias;
        }
    }
    __syncthreads();   // s_raw visible to all (stage-in also done by now)

    if (tid == 0) {
        const float scale = 2.0f / (1.0f + expf(-s_raw[0]));
        const float ang = tanhf(s_raw[1]) * PI_C;
        const float a = cosf(ang) * scale;
        const float s = sinf(ang) * scale;
        const float tx = tanhf(s_raw[2]);
        const float ty = tanhf(s_raw[3]);
        const float k64 = 64.0f * (2.0f / 127.0f);
        s_cf[0] = a * k64;                        // Ax
        s_cf[1] = -s * k64;                       // Ay
        s_cf[2] = (tx - a + s) * 64.0f + 63.5f;   // A0
        s_cf[3] = s * k64;                        // Bx
        s_cf[4] = a * k64;                        // By
        s_cf[5] = (ty - s - a) * 64.0f + 63.5f;   // B0
    }
    __syncthreads();

    const float Ax = s_cf[0], Ay = s_cf[1], A0 = s_cf[2];
    const float Bx = s_cf[3], By = s_cf[4], B0 = s_cf[5];

    // ---- sampling: 4-pixel quads, float4 stores, incremental affine ----
    float4* __restrict__ o4 = (float4*)(out + (size_t)n * 16384);
    #pragma unroll 2
    for (int i = tid; i < 4096; i += 512) {
        const float xq = (float)((i & 31) << 2);
        const float fy = (float)(i >> 5);
        float px0 = fmaf(Ax, xq, fmaf(Ay, fy, A0));
        float py0 = fmaf(Bx, xq, fmaf(By, fy, B0));
        float4 r;
        float* rp = &r.x;
        #pragma unroll
        for (int q = 0; q < 4; ++q) {
            float px = fminf(fmaxf(px0, 0.0f), 127.0f);   // border clamp
            float py = fminf(fmaxf(py0, 0.0f), 127.0f);
            px0 += Ax;                                    // next pixel in quad
            py0 += Bx;
            const float x0f = floorf(px);
            const float y0f = floorf(py);
            const float wx = px - x0f;
            const float wy = py - y0f;
            const int x0 = (int)x0f;
            const int y0 = (int)y0f;
            const int x1 = min(x0 + 1, 127);
            const int y1 = min(y0 + 1, 127);
            const int r0 = y0 * TILE_PITCH;
            const int r1 = y1 * TILE_PITCH;
            const float v00 = tile[r0 + x0];
            const float v01 = tile[r0 + x1];
            const float v10 = tile[r1 + x0];
            const float v11 = tile[r1 + x1];
            const float top = fmaf(wx, v01 - v00, v00);
            const float bot = fmaf(wx, v11 - v10, v10);
            rp[q] = fmaf(wy, bot - top, top);
        }
        o4[i] = r;
    }
}

// ---------------- launch -----------------------------------------------------
extern "C" void kernel_launch(void* const* d_in, const int* in_sizes, int n_in,
                              void* d_out, int out_size) {
    const float* feature_map = (const float*)d_in[0];   // (8,256,128,128)
    const float* para_code   = (const float*)d_in[1];   // (8,256)
    const float* W1 = (const float*)d_in[2];            // (256,256)
    const float* b1 = (const float*)d_in[3];            // (256,)
    const float* Ws = (const float*)d_in[4];            // (256,256)
    const float* bs = (const float*)d_in[5];            // (256,)
    const float* Wr = (const float*)d_in[6];            // (256,256)
    const float* br = (const float*)d_in[7];            // (256,)
    const float* Wt = (const float*)d_in[8];            // (256,512)
    const float* bt = (const float*)d_in[9];            // (512,)
    float* out = (float*)d_out;

    cudaFuncSetAttribute(resample_kernel,
                         cudaFuncAttributeMaxDynamicSharedMemorySize, TILE_BYTES);

    mlp1_partial_kernel<<<dim3(8, 4), 256>>>(para_code, W1, b1);
    resample_kernel<<<2048, 512, TILE_BYTES>>>(feature_map, out,
                                               Ws, bs, Wr, br, Wt, bt);
}

// round 12
// speedup vs baseline: 1.0957x; 1.0761x over previous
#include <cuda_runtime.h>
#include <math.h>

#define PI_C 3.14159f
#define TILE_PITCH 129                     // 129 % 32 == 1: vertical stride conflict-free
#define TILE_BYTES (128 * TILE_PITCH * 4)  // 66048

// ---------------- scratch (allocation-free rule: __device__ globals) --------
// mlp1 partial sums: [kc][b*256+j], kc in 0..3 (kc=0 includes bias b1)
__device__ float g_p1[4 * 8 * 256];
// transposed mlp2 weights: [f][d][k], f in {s, r, t0, t1}
__device__ float g_wT[4 * 256 * 256];

// ---------------- kernel 1: prep = mlp1 partials + weight transpose --------
// grid 288 x 256 threads.
//   blocks 0..31:   mlp1 partial (jc = bid&7, kc = bid>>3)
//   blocks 32..287: 32x32 transpose tiles of the 4 weight families
__global__ void prep_kernel(const float* __restrict__ pc,
                            const float* __restrict__ W1,
                            const float* __restrict__ b1,
                            const float* __restrict__ Ws,
                            const float* __restrict__ Wr,
                            const float* __restrict__ Wt) {
    const int tid = threadIdx.x;
    const int bid = blockIdx.x;

    if (bid < 32) {
        // ---- mlp1 partial: 32 j-cols, 64-k slice, 8 batches in registers ----
        __shared__ float spc[8 * 64];
        __shared__ float part[8 * 8 * 32];
        const int jl = tid & 31;
        const int ks = tid >> 5;
        const int jc = bid & 7;
        const int kc = bid >> 3;
        const int j = jc * 32 + jl;
        const int kbase = kc * 64;

        #pragma unroll
        for (int i = tid; i < 512; i += 256)
            spc[i] = pc[(i >> 6) * 256 + kbase + (i & 63)];
        __syncthreads();

        float acc[8];
        #pragma unroll
        for (int b = 0; b < 8; ++b) acc[b] = 0.0f;

        #pragma unroll
        for (int kk = 0; kk < 8; ++kk) {
            const int kl = ks * 8 + kk;
            const float w = W1[(kbase + kl) * 256 + j];
            #pragma unroll
            for (int b = 0; b < 8; ++b) acc[b] = fmaf(spc[b * 64 + kl], w, acc[b]);
        }
        #pragma unroll
        for (int b = 0; b < 8; ++b) part[(ks * 8 + b) * 32 + jl] = acc[b];
        __syncthreads();

        const int jl2 = tid & 31;
        const int b2 = tid >> 5;
        float sum = (kc == 0) ? b1[jc * 32 + jl2] : 0.0f;
        #pragma unroll
        for (int k2 = 0; k2 < 8; ++k2) sum += part[(k2 * 8 + b2) * 32 + jl2];
        g_p1[kc * 2048 + b2 * 256 + jc * 32 + jl2] = sum;
    } else {
        // ---- weight transpose: g_wT[f][d][k] = W_f[k][d] ----
        __shared__ float t[32][33];
        const int tb = bid - 32;
        const int f = tb >> 6;                 // 4 families x 64 tiles
        const int t6 = tb & 63;
        const int d0 = (t6 & 7) * 32;
        const int k0 = (t6 >> 3) * 32;
        const int tx = tid & 31;
        const int ty = tid >> 5;               // 0..7

        #pragma unroll
        for (int jj = 0; jj < 4; ++jj) {
            const int k = k0 + ty + 8 * jj;
            const int d = d0 + tx;
            float v;
            if (f == 0)      v = Ws[k * 256 + d];
            else if (f == 1) v = Wr[k * 256 + d];
            else if (f == 2) v = Wt[k * 512 + 2 * d];
            else             v = Wt[k * 512 + 2 * d + 1];
            t[ty + 8 * jj][tx] = v;
        }
        __syncthreads();
        #pragma unroll
        for (int jj = 0; jj < 4; ++jj) {
            const int d = d0 + ty + 8 * jj;
            const int k = k0 + tx;
            g_wT[f * 65536 + d * 256 + k] = t[tx][ty + 8 * jj];
        }
    }
}

// ---------------- kernel 2: fused params + affine bilinear resample ---------
// grid: B*D = 2048 blocks, 512 threads, pitched 66KB smem tile.
// All SMEM traffic is lane-stride-1 (conflict-free with odd pitch).
__global__ __launch_bounds__(512) void resample_kernel(
        const float* __restrict__ fm, float* __restrict__ out,
        const float* __restrict__ bs, const float* __restrict__ br,
        const float* __restrict__ bt) {
    extern __shared__ float tile[];           // 128 rows x 129 pitch
    __shared__ float s_raw[4];
    __shared__ float s_cf[6];                 // Ax, Ay, A0, Bx, By, B0
    const int n = blockIdx.x;                 // n = b*256 + d
    const int tid = threadIdx.x;
    const int b = n >> 8;
    const int d = n & 255;
    const float* __restrict__ img = fm + (size_t)n * 16384;

    // ---- stage-in: scalar, lane-stride-1 -> coalesced LDG, conflict-free STS
    #pragma unroll 8
    for (int i = tid; i < 16384; i += 512)
        tile[(i >> 7) * TILE_PITCH + (i & 127)] = img[i];

    // ---- param dot-products on warps 0-3 (one family each), overlapped ----
    if (tid < 128) {
        const int f = tid >> 5;               // family: s, r, t0, t1
        const int lane = tid & 31;
        const float* __restrict__ pp = g_p1 + b * 256;
        const float* __restrict__ wt = g_wT + f * 65536 + d * 256;

        float acc = 0.0f;
        #pragma unroll
        for (int i = 0; i < 8; ++i) {
            const int k = lane + 32 * i;      // lane-consecutive -> coalesced
            float pk = pp[k] + pp[2048 + k] + pp[2 * 2048 + k] + pp[3 * 2048 + k];
            pk = fmaxf(pk, 0.0f);             // relu(b1 + full k-sum)
            acc = fmaf(pk, wt[k], acc);
        }
        #pragma unroll
        for (int o = 16; o > 0; o >>= 1)
            acc += __shfl_xor_sync(0xFFFFFFFFu, acc, o);

        if (lane == 0) {
            float bias;
            if (f == 0)      bias = bs[d];
            else if (f == 1) bias = br[d];
            else if (f == 2) bias = bt[2 * d];
            else             bias = bt[2 * d + 1];
            s_raw[f] = acc + bias;
        }
    }
    __syncthreads();   // s_raw visible; stage-in also complete

    if (tid == 0) {
        const float scale = 2.0f / (1.0f + expf(-s_raw[0]));
        const float ang = tanhf(s_raw[1]) * PI_C;
        const float a = cosf(ang) * scale;
        const float s = sinf(ang) * scale;
        const float tx = tanhf(s_raw[2]);
        const float ty = tanhf(s_raw[3]);
        const float k64 = 64.0f * (2.0f / 127.0f);
        s_cf[0] = a * k64;                        // Ax
        s_cf[1] = -s * k64;                       // Ay
        s_cf[2] = (tx - a + s) * 64.0f + 63.5f;   // A0
        s_cf[3] = s * k64;                        // Bx
        s_cf[4] = a * k64;                        // By
        s_cf[5] = (ty - s - a) * 64.0f + 63.5f;   // B0
    }
    __syncthreads();

    const float Ax = s_cf[0], Ay = s_cf[1], A0 = s_cf[2];
    const float Bx = s_cf[3], By = s_cf[4], B0 = s_cf[5];

    // ---- sampling: 1 pixel/lane, lane-stride-1 in x -> conflict-free LDS ----
    float* __restrict__ o = out + (size_t)n * 16384;
    #pragma unroll 4
    for (int idx = tid; idx < 16384; idx += 512) {
        const float x = (float)(idx & 127);
        const float y = (float)(idx >> 7);
        float px = fmaf(Ax, x, fmaf(Ay, y, A0));
        float py = fmaf(Bx, x, fmaf(By, y, B0));
        px = fminf(fmaxf(px, 0.0f), 127.0f);   // padding_mode='border'
        py = fminf(fmaxf(py, 0.0f), 127.0f);
        const float x0f = floorf(px);
        const float y0f = floorf(py);
        const float wx = px - x0f;
        const float wy = py - y0f;
        const int x0 = (int)x0f;
        const int y0 = (int)y0f;
        const int x1 = min(x0 + 1, 127);
        const int y1 = min(y0 + 1, 127);
        const int r0 = y0 * TILE_PITCH;
        const int r1 = y1 * TILE_PITCH;
        const float v00 = tile[r0 + x0];
        const float v01 = tile[r0 + x1];
        const float v10 = tile[r1 + x0];
        const float v11 = tile[r1 + x1];
        const float top = fmaf(wx, v01 - v00, v00);
        const float bot = fmaf(wx, v11 - v10, v10);
        o[idx] = fmaf(wy, bot - top, top);
    }
}

// ---------------- launch -----------------------------------------------------
extern "C" void kernel_launch(void* const* d_in, const int* in_sizes, int n_in,
                              void* d_out, int out_size) {
    const float* feature_map = (const float*)d_in[0];   // (8,256,128,128)
    const float* para_code   = (const float*)d_in[1];   // (8,256)
    const float* W1 = (const float*)d_in[2];            // (256,256)
    const float* b1 = (const float*)d_in[3];            // (256,)
    const float* Ws = (const float*)d_in[4];            // (256,256)
    const float* bs = (const float*)d_in[5];            // (256,)
    const float* Wr = (const float*)d_in[6];            // (256,256)
    const float* br = (const float*)d_in[7];            // (256,)
    const float* Wt = (const float*)d_in[8];            // (256,512)
    const float* bt = (const float*)d_in[9];            // (512,)
    float* out = (float*)d_out;

    cudaFuncSetAttribute(resample_kernel,
                         cudaFuncAttributeMaxDynamicSharedMemorySize, TILE_BYTES);

    prep_kernel<<<288, 256>>>(para_code, W1, b1, Ws, Wr, Wt);
    resample_kernel<<<2048, 512, TILE_BYTES>>>(feature_map, out, bs, br, bt);
}